// round 14
// baseline (speedup 1.0000x reference)
#include <cuda_runtime.h>

// B=8192, L=64, Cin=8, KS=4, trunc=9, Lo=55, Caug=11, DEPTH=3
// sig = 11 + 121 + 1331 = 1463 channels; head 1463 -> 10
#define WARPS    4
#define NTHREADS (32 * WARPS)
#define LFULL    64
#define CIN      8
#define LO       55
#define CC       11
#define CC2      121
#define SIGCH    1463
#define SIGPAD   1536            // 12 * 128
#define NSTOCK   10

// per-warp shared region (floats); rows pitched 68 (16B-aligned float4 rows)
#define WROW     68
#define XS_OFF   0               // x transposed [c][t], 8*68
#define H1_OFF   544             // conv1 out, 8*68
#define H2_OFF   1088            // conv2 out, 8*68
#define H3_OFF   1632            // conv3 out, 2*56
#define DXS_OFF  544             // aliases H1/H2 (dead after conv3), 55*12
#define SIG_OFF  0               // aliases XS/H1/DXS after main loop, 1536
#define WARP_FLTS 1744

__device__ __align__(16) float g_WlPad[NSTOCK * SIGPAD];

__global__ void wl_pad_kernel(const float* __restrict__ Wl)
{
    int idx = blockIdx.x * blockDim.x + threadIdx.x;
    if (idx < NSTOCK * SIGPAD) {
        int s = idx / SIGPAD, c = idx - s * SIGPAD;
        g_WlPad[idx] = (c < SIGCH) ? Wl[s * SIGCH + c] : 0.0f;
    }
}

__device__ __forceinline__ unsigned long long pack2(float lo, float hi)
{
    unsigned long long r;
    asm("mov.b64 %0, {%1, %2};" : "=l"(r) : "f"(lo), "f"(hi));
    return r;
}
__device__ __forceinline__ void unpack2(unsigned long long v, float& lo, float& hi)
{
    asm("mov.b64 {%0, %1}, %2;" : "=f"(lo), "=f"(hi) : "l"(v));
}
__device__ __forceinline__ void fma2(unsigned long long& d,
                                     unsigned long long a, unsigned long long b)
{
    asm("fma.rn.f32x2 %0, %1, %2, %0;" : "+l"(d) : "l"(a), "l"(b));
}

__global__ void __launch_bounds__(NTHREADS, 5)
deepsig_kernel(const float* __restrict__ x,
               const float* __restrict__ W1, const float* __restrict__ b1,
               const float* __restrict__ W2, const float* __restrict__ b2,
               const float* __restrict__ W3, const float* __restrict__ b3,
               const float* __restrict__ bl,
               float* __restrict__ out, int B)
{
    __shared__ __align__(16) float wmem[WARPS * WARP_FLTS];
    // conv weights as replicated pairs (w,w): layout [o][i][k] (native order)
    __shared__ __align__(16) unsigned long long w1p[256], w2p[256], w3p[64];
    __shared__ float b1s[8], b2s[8], b3s[2];

    const int tid  = threadIdx.x;
    const int warp = tid >> 5;
    const int lane = tid & 31;

    for (int i = tid; i < 256; i += NTHREADS) {
        float v1 = W1[i], v2 = W2[i];
        w1p[i] = pack2(v1, v1);
        w2p[i] = pack2(v2, v2);
    }
    for (int i = tid; i < 64; i += NTHREADS) {
        float v3 = W3[i];
        w3p[i] = pack2(v3, v3);
    }
    if (tid < 8) { b1s[tid] = b1[tid]; b2s[tid] = b2[tid]; }
    if (tid < 2) { b3s[tid] = b3[tid]; }
    __syncthreads();

    const int b = blockIdx.x * WARPS + warp;
    const bool bvalid = (b < B);

    float* S = wmem + warp * WARP_FLTS;

    if (bvalid) {
        // ---- Load x (float4, coalesced), transpose into [c][t] pitch 68 ----
        const float4* xb4 = (const float4*)(x + (size_t)b * (LFULL * CIN));
        #pragma unroll
        for (int it = 0; it < 4; it++) {
            int idx = (lane + it * 32);
            int t = idx >> 1, c = (idx & 1) * 4;
            float4 v = xb4[idx];
            S[XS_OFF + (c + 0) * WROW + t] = v.x;
            S[XS_OFF + (c + 1) * WROW + t] = v.y;
            S[XS_OFF + (c + 2) * WROW + t] = v.z;
            S[XS_OFF + (c + 3) * WROW + t] = v.w;
        }
        __syncwarp();

        // ---- conv1 (relu): XS -> H1, Lout=61; even/odd-k packed pairs ----
        // accA[p]: positions (2p,2p+1), even k; accB[q]: (2q-1,2q), odd k.
        {
            const float* in = S + XS_OFF;
            float* outp = S + H1_OFF;
            int o = lane >> 2, g = lane & 3, t0 = g * 16;
            int count = 61 - t0; if (count > 16) count = 16;
            unsigned long long accA[8], accB[9];
            #pragma unroll
            for (int p = 0; p < 8; p++) accA[p] = 0ULL;
            #pragma unroll
            for (int q = 0; q < 9; q++) accB[q] = 0ULL;
            for (int i = 0; i < 8; i++) {
                unsigned long long xq[10];
                const ulonglong2* pp = (const ulonglong2*)(in + i * WROW + t0);
                #pragma unroll
                for (int q = 0; q < 5; q++) {
                    ulonglong2 v = pp[q];
                    xq[2 * q] = v.x; xq[2 * q + 1] = v.y;
                }
                const ulonglong2* wq = (const ulonglong2*)(w1p + (o * 8 + i) * 4);
                ulonglong2 wa = wq[0], wb = wq[1];   // k0,k1 / k2,k3
                #pragma unroll
                for (int p = 0; p < 8; p++) {
                    fma2(accA[p], xq[p],     wa.x);  // k=0
                    fma2(accA[p], xq[p + 1], wb.x);  // k=2
                }
                #pragma unroll
                for (int q = 0; q < 9; q++) {
                    fma2(accB[q], xq[q],     wa.y);  // k=1
                    fma2(accB[q], xq[q + 1], wb.y);  // k=3
                }
            }
            float bo = b1s[o];
            #pragma unroll
            for (int p = 0; p < 8; p++) {
                float aL, aH, bL, bH, cL, cH;
                unpack2(accA[p], aL, aH);
                unpack2(accB[p], bL, bH);
                unpack2(accB[p + 1], cL, cH);
                int tt = 2 * p;
                if (tt < count)
                    outp[o * WROW + t0 + tt] = fmaxf(aL + bH + bo, 0.0f);
                if (tt + 1 < count)
                    outp[o * WROW + t0 + tt + 1] = fmaxf(aH + cL + bo, 0.0f);
            }
        }
        __syncwarp();
        // ---- conv2 (relu): H1 -> H2, Lout=58 ----
        {
            const float* in = S + H1_OFF;
            float* outp = S + H2_OFF;
            int o = lane >> 2, g = lane & 3, t0 = g * 16;
            int count = 58 - t0; if (count > 16) count = 16;
            unsigned long long accA[8], accB[9];
            #pragma unroll
            for (int p = 0; p < 8; p++) accA[p] = 0ULL;
            #pragma unroll
            for (int q = 0; q < 9; q++) accB[q] = 0ULL;
            for (int i = 0; i < 8; i++) {
                unsigned long long xq[10];
                const ulonglong2* pp = (const ulonglong2*)(in + i * WROW + t0);
                #pragma unroll
                for (int q = 0; q < 5; q++) {
                    ulonglong2 v = pp[q];
                    xq[2 * q] = v.x; xq[2 * q + 1] = v.y;
                }
                const ulonglong2* wq = (const ulonglong2*)(w2p + (o * 8 + i) * 4);
                ulonglong2 wa = wq[0], wb = wq[1];
                #pragma unroll
                for (int p = 0; p < 8; p++) {
                    fma2(accA[p], xq[p],     wa.x);
                    fma2(accA[p], xq[p + 1], wb.x);
                }
                #pragma unroll
                for (int q = 0; q < 9; q++) {
                    fma2(accB[q], xq[q],     wa.y);
                    fma2(accB[q], xq[q + 1], wb.y);
                }
            }
            float bo = b2s[o];
            #pragma unroll
            for (int p = 0; p < 8; p++) {
                float aL, aH, bL, bH, cL, cH;
                unpack2(accA[p], aL, aH);
                unpack2(accB[p], bL, bH);
                unpack2(accB[p + 1], cL, cH);
                int tt = 2 * p;
                if (tt < count)
                    outp[o * WROW + t0 + tt] = fmaxf(aL + bH + bo, 0.0f);
                if (tt + 1 < count)
                    outp[o * WROW + t0 + tt + 1] = fmaxf(aH + cL + bo, 0.0f);
            }
        }
        __syncwarp();
        // ---- conv3 (no relu): H2 -> H3, Lout=55; 4 positions/lane ----
        {
            const float* in = S + H2_OFF;
            float* outp = S + H3_OFF;
            int o = lane >> 4, g = lane & 15, t0 = g * 4;
            int count = 55 - t0; count = count > 4 ? 4 : (count < 0 ? 0 : count);
            unsigned long long accA[2], accB[3];
            accA[0] = accA[1] = 0ULL;
            accB[0] = accB[1] = accB[2] = 0ULL;
            for (int i = 0; i < 8; i++) {
                unsigned long long xq[4];
                const ulonglong2* pp = (const ulonglong2*)(in + i * WROW + t0);
                ulonglong2 v0 = pp[0], v1 = pp[1];
                xq[0] = v0.x; xq[1] = v0.y; xq[2] = v1.x; xq[3] = v1.y;
                const ulonglong2* wq = (const ulonglong2*)(w3p + (o * 8 + i) * 4);
                ulonglong2 wa = wq[0], wb = wq[1];
                #pragma unroll
                for (int p = 0; p < 2; p++) {
                    fma2(accA[p], xq[p],     wa.x);
                    fma2(accA[p], xq[p + 1], wb.x);
                }
                #pragma unroll
                for (int q = 0; q < 3; q++) {
                    fma2(accB[q], xq[q],     wa.y);
                    fma2(accB[q], xq[q + 1], wb.y);
                }
            }
            float bo = b3s[o];
            #pragma unroll
            for (int p = 0; p < 2; p++) {
                float aL, aH, bL, bH, cL, cH;
                unpack2(accA[p], aL, aH);
                unpack2(accB[p], bL, bH);
                unpack2(accB[p + 1], cL, cH);
                int tt = 2 * p;
                if (tt < count)
                    outp[o * 56 + t0 + tt] = aL + bH + bo;
                if (tt + 1 < count)
                    outp[o * 56 + t0 + tt + 1] = aH + cL + bo;
            }
        }
        __syncwarp();
    }

    // ---- sig1 endpoint captured before aliasing ----
    float sig1v = 0.0f;
    if (bvalid && lane < CC) {
        if (lane < 8)       sig1v = S[XS_OFF + lane * WROW + 63];
        else if (lane == 8) sig1v = 1.0f;
        else                sig1v = S[H3_OFF + (lane - 9) * 56 + 54];
    }

    // ---- i-fixed slot map: lane owns (i_lane, j = 4*quad + m), m=0..3.
    //      lanes 0-10: i=lane,  j 0-3 ; 11-21: i=lane-11, j 4-7 ;
    //      22-31: i=lane-22, j 8-11 (j=11 reads pad 0 -> exact no-op).
    //      Missing slots (10,8),(10,9),(10,10) -> shuffle-identity epilogue. ----
    const int quad   = (lane < 11) ? 0 : (lane < 22) ? 1 : 2;
    const int i_lane = lane - 11 * quad;

    float s1i = 0.0f;
    float s2[4] = {0.f, 0.f, 0.f, 0.f};
    unsigned long long s3p[4][6];
    #pragma unroll
    for (int m = 0; m < 4; m++)
        #pragma unroll
        for (int q = 0; q < 6; q++) s3p[m][q] = 0ULL;

    if (bvalid) {
        // ---- dx[t][c] (c=0..10, col 11 = 0 pad) into DXS ----
        for (int idx = lane; idx < 55 * 12; idx += 32) {
            int t = idx / 12, c = idx - t * 12;
            float v;
            if (c < 8) {
                v = (t == 0) ? S[XS_OFF + c * WROW + 9]
                             : S[XS_OFF + c * WROW + 9 + t] - S[XS_OFF + c * WROW + 8 + t];
            } else if (c == 8) {
                v = (t == 0) ? 0.0f : (1.0f / 54.0f);
            } else if (c < 11) {
                int o = c - 9;
                v = (t == 0) ? S[H3_OFF + o * 56]
                             : S[H3_OFF + o * 56 + t] - S[H3_OFF + o * 56 + t - 1];
            } else {
                v = 0.0f;
            }
            S[DXS_OFF + idx] = v;
        }
        __syncwarp();

        // ---- signature main loop (factored Chen, packed f32x2), unroll 5 ----
        const float* dxbase = S + DXS_OFF;
        #pragma unroll 5
        for (int t = 0; t < LO; t++) {
            const float* row = dxbase + t * 12;
            ulonglong2 a0 = *(const ulonglong2*)(row);
            ulonglong2 a1 = *(const ulonglong2*)(row + 4);
            ulonglong2 a2 = *(const ulonglong2*)(row + 8);
            unsigned long long dp[6] = {a0.x, a0.y, a1.x, a1.y, a2.x, a2.y};
            float4 djv = *(const float4*)(row + 4 * quad);
            float di = row[i_lane];

            float c1 = fmaf(1.0f / 6.0f, di, 0.5f * s1i);
            float c2 = fmaf(0.5f, di, s1i);
            s1i += di;

            float dj[4] = {djv.x, djv.y, djv.z, djv.w};
            #pragma unroll
            for (int m = 0; m < 4; m++) {
                float Mv = fmaf(dj[m], c1, s2[m]);
                s2[m]    = fmaf(dj[m], c2, s2[m]);
                unsigned long long mvp = pack2(Mv, Mv);
                #pragma unroll
                for (int q = 0; q < 6; q++)
                    fma2(s3p[m][q], dp[q], mvp);
            }
        }
        __syncwarp();

        // ---- scatter signature to shared (conflict-free) ----
        float* sig = S + SIG_OFF;
        if (lane < CC) sig[lane] = sig1v;
        for (int z = SIGCH + lane; z < SIGPAD; z += 32) sig[z] = 0.0f;
        #pragma unroll
        for (int m = 0; m < 4; m++) {
            int j = 4 * quad + m;
            if (j < CC) {
                int ij = i_lane * 11 + j;
                sig[CC + ij] = s2[m];
                #pragma unroll
                for (int q = 0; q < 6; q++) {
                    float lo, hi;
                    unpack2(s3p[m][q], lo, hi);
                    int k = 2 * q;
                    sig[CC + CC2 + ij * 11 + k] = lo;
                    if (k + 1 < 11) sig[CC + CC2 + ij * 11 + k + 1] = hi;
                }
            }
        }
        __syncwarp();

        // ---- shuffle-identity reconstruction of (10,8),(10,9),(10,10) ----
        {
            float* sg2 = sig + CC;
            float* sg3 = sig + CC + CC2;
            float s1_10 = sig[10];
            // step1: s2[10,k] for k = 8,9,10 via s2[ab]+s2[ba]=s1a*s1b
            if (lane >= 8 && lane < CC) {
                int k = lane;
                float v = (k == 10) ? 0.5f * s1_10 * s1_10
                                    : s1_10 * sig[k] - sg2[k * 11 + 10];
                sg2[110 + k] = v;
            }
            __syncwarp();
            // step2: s3[10,j,k] = s1_10*s2[j,k] - s3[j,10,k] - s3[j,k,10], j=8,9
            if (lane < CC) {
                int k = lane;
                #pragma unroll
                for (int j = 8; j <= 9; j++) {
                    float v = s1_10 * sg2[j * 11 + k]
                            - sg3[(j * 11 + 10) * 11 + k]
                            - sg3[(j * 11 + k) * 11 + 10];
                    sg3[(110 + j) * 11 + k] = v;
                }
            }
            __syncwarp();
            // step3: s3[10,10,k] = (s1_10*s2[10,k] - s3[10,k,10]) / 2 ; k=10: s1*s2[10,10]/3
            if (lane < CC) {
                int k = lane;
                float v;
                if (k == 10) v = s1_10 * sg2[120] * (1.0f / 3.0f);
                else         v = 0.5f * (s1_10 * sg2[110 + k]
                                         - sg3[(110 + k) * 11 + 10]);
                sg3[120 * 11 + k] = v;
            }
        }
    }
    __syncthreads();

    // ---- block-cooperative head: warps split stocks {3,3,2,2}; each warp
    //      applies its stocks' weights to ALL 4 batch sigs (Wl read once).
    //      128-bit loads: 4 channels/lane/iter. ----
    const int s_base = (warp < 2) ? warp * 3 : 6 + (warp - 2) * 2;
    const int n_s    = (warp < 2) ? 3 : 2;

    unsigned long long acc[4][3];
    #pragma unroll
    for (int bb = 0; bb < 4; bb++)
        #pragma unroll
        for (int sl = 0; sl < 3; sl++) acc[bb][sl] = 0ULL;

    const float* wl = g_WlPad;
    #pragma unroll 4
    for (int it = 0; it < SIGPAD / 128; it++) {
        int c = 4 * lane + 128 * it;
        ulonglong2 vp[4];
        #pragma unroll
        for (int bb = 0; bb < 4; bb++)
            vp[bb] = *(const ulonglong2*)(wmem + bb * WARP_FLTS + SIG_OFF + c);
        #pragma unroll
        for (int sl = 0; sl < 3; sl++) {
            if (sl < n_s) {
                ulonglong2 wp =
                    *(const ulonglong2*)(wl + (s_base + sl) * SIGPAD + c);
                #pragma unroll
                for (int bb = 0; bb < 4; bb++) {
                    fma2(acc[bb][sl], vp[bb].x, wp.x);
                    fma2(acc[bb][sl], vp[bb].y, wp.y);
                }
            }
        }
    }

    #pragma unroll
    for (int bb = 0; bb < 4; bb++) {
        int bg = blockIdx.x * WARPS + bb;
        #pragma unroll
        for (int sl = 0; sl < 3; sl++) {
            if (sl < n_s) {
                float lo, hi;
                unpack2(acc[bb][sl], lo, hi);
                float v = lo + hi;
                #pragma unroll
                for (int off = 16; off > 0; off >>= 1)
                    v += __shfl_xor_sync(0xffffffffu, v, off);
                if (lane == 0 && bg < B)
                    out[bg * NSTOCK + s_base + sl] = v + __ldg(&bl[s_base + sl]);
            }
        }
    }
}

extern "C" void kernel_launch(void* const* d_in, const int* in_sizes, int n_in,
                              void* d_out, int out_size)
{
    const float* x  = (const float*)d_in[0];
    const float* W1 = (const float*)d_in[1];
    const float* b1 = (const float*)d_in[2];
    const float* W2 = (const float*)d_in[3];
    const float* b2 = (const float*)d_in[4];
    const float* W3 = (const float*)d_in[5];
    const float* b3 = (const float*)d_in[6];
    const float* Wl = (const float*)d_in[7];
    const float* bl = (const float*)d_in[8];
    float* out = (float*)d_out;

    int B = in_sizes[0] / (LFULL * CIN);   // 8192

    wl_pad_kernel<<<(NSTOCK * SIGPAD + 255) / 256, 256>>>(Wl);

    int blocks = (B + WARPS - 1) / WARPS;
    deepsig_kernel<<<blocks, NTHREADS>>>(x, W1, b1, W2, b2, W3, b3, bl, out, B);
}

// round 15
// speedup vs baseline: 1.0758x; 1.0758x over previous
#include <cuda_runtime.h>

// B=8192, L=64, Cin=8, KS=4, trunc=9, Lo=55, Caug=11, DEPTH=3
// sig = 11 + 121 + 1331 = 1463 channels; head 1463 -> 10
#define WARPS    4
#define NTHREADS (32 * WARPS)
#define LFULL    64
#define CIN      8
#define LO       55
#define CC       11
#define CC2      121
#define SIGCH    1463
#define SIGPAD   1536            // 12 * 128
#define NSTOCK   10

// per-warp shared region (floats); rows pitched 68 (16B-aligned float4 rows)
#define WROW     68
#define XS_OFF   0               // x transposed [c][t], 8*68
#define H1_OFF   544             // conv1 out, 8*68
#define H2_OFF   1088            // conv2 out, 8*68
#define H3_OFF   1632            // conv3 out, 2*56
#define DXS_OFF  544             // aliases H1/H2 (dead after conv3), 55*12
#define SIG_OFF  0               // aliases XS/H1/DXS after main loop, 1536
#define WARP_FLTS 1744

__device__ __align__(16) float g_WlPad[NSTOCK * SIGPAD];

__global__ void wl_pad_kernel(const float* __restrict__ Wl)
{
    int idx = blockIdx.x * blockDim.x + threadIdx.x;
    if (idx < NSTOCK * SIGPAD) {
        int s = idx / SIGPAD, c = idx - s * SIGPAD;
        g_WlPad[idx] = (c < SIGCH) ? Wl[s * SIGCH + c] : 0.0f;
    }
}

__device__ __forceinline__ unsigned long long pack2(float lo, float hi)
{
    unsigned long long r;
    asm("mov.b64 %0, {%1, %2};" : "=l"(r) : "f"(lo), "f"(hi));
    return r;
}
__device__ __forceinline__ void unpack2(unsigned long long v, float& lo, float& hi)
{
    asm("mov.b64 {%0, %1}, %2;" : "=f"(lo), "=f"(hi) : "l"(v));
}
__device__ __forceinline__ void fma2(unsigned long long& d,
                                     unsigned long long a, unsigned long long b)
{
    asm("fma.rn.f32x2 %0, %1, %2, %0;" : "+l"(d) : "l"(a), "l"(b));
}

__global__ void __launch_bounds__(NTHREADS, 5)
deepsig_kernel(const float* __restrict__ x,
               const float* __restrict__ W1, const float* __restrict__ b1,
               const float* __restrict__ W2, const float* __restrict__ b2,
               const float* __restrict__ W3, const float* __restrict__ b3,
               const float* __restrict__ bl,
               float* __restrict__ out, int B)
{
    __shared__ __align__(16) float wmem[WARPS * WARP_FLTS];
    __shared__ float w1s[256], w2s[256], w3s[64], b1s[8], b2s[8], b3s[2];

    const int tid  = threadIdx.x;
    const int warp = tid >> 5;
    const int lane = tid & 31;

    // Stage conv weights transposed: ws[(i*4+k)*OC + o] = W[o][i][k]
    for (int i = tid; i < 256; i += NTHREADS) {
        int o = i >> 5, r = i & 31;
        w1s[r * 8 + o] = W1[i];
        w2s[r * 8 + o] = W2[i];
    }
    for (int i = tid; i < 64; i += NTHREADS) {
        int o = i >> 5, r = i & 31;
        w3s[r * 2 + o] = W3[i];
    }
    if (tid < 8) { b1s[tid] = b1[tid]; b2s[tid] = b2[tid]; }
    if (tid < 2) { b3s[tid] = b3[tid]; }
    __syncthreads();

    const int b = blockIdx.x * WARPS + warp;
    const bool bvalid = (b < B);

    float* S = wmem + warp * WARP_FLTS;

    if (bvalid) {
        // ---- Load x (float4, coalesced), transpose into [c][t] pitch 68 ----
        const float4* xb4 = (const float4*)(x + (size_t)b * (LFULL * CIN));
        #pragma unroll
        for (int it = 0; it < 4; it++) {
            int idx = (lane + it * 32);
            int t = idx >> 1, c = (idx & 1) * 4;
            float4 v = xb4[idx];
            S[XS_OFF + (c + 0) * WROW + t] = v.x;
            S[XS_OFF + (c + 1) * WROW + t] = v.y;
            S[XS_OFF + (c + 2) * WROW + t] = v.z;
            S[XS_OFF + (c + 3) * WROW + t] = v.w;
        }
        __syncwarp();

        // ---- conv1 (relu): XS -> H1, Lout=61; window = 5x LDS.128 ----
        {
            const float* in = S + XS_OFF;
            float* outp = S + H1_OFF;
            int o = lane >> 2, g = lane & 3, t0 = g * 16;
            int count = 61 - t0; if (count > 16) count = 16;
            float acc[16];
            #pragma unroll
            for (int tt = 0; tt < 16; tt++) acc[tt] = 0.0f;
            for (int i = 0; i < 8; i++) {
                float xv[20];
                const float4* p = (const float4*)(in + i * WROW + t0);
                #pragma unroll
                for (int q = 0; q < 5; q++) {
                    float4 v = p[q];
                    xv[4*q+0] = v.x; xv[4*q+1] = v.y;
                    xv[4*q+2] = v.z; xv[4*q+3] = v.w;
                }
                #pragma unroll
                for (int k = 0; k < 4; k++) {
                    float wk = w1s[(i * 4 + k) * 8 + o];
                    #pragma unroll
                    for (int tt = 0; tt < 16; tt++)
                        acc[tt] = fmaf(xv[tt + k], wk, acc[tt]);
                }
            }
            float bo = b1s[o];
            #pragma unroll
            for (int tt = 0; tt < 16; tt++)
                if (tt < count) outp[o * WROW + t0 + tt] = fmaxf(acc[tt] + bo, 0.0f);
        }
        __syncwarp();
        // ---- conv2 (relu): H1 -> H2, Lout=58 ----
        {
            const float* in = S + H1_OFF;
            float* outp = S + H2_OFF;
            int o = lane >> 2, g = lane & 3, t0 = g * 16;
            int count = 58 - t0; if (count > 16) count = 16;
            float acc[16];
            #pragma unroll
            for (int tt = 0; tt < 16; tt++) acc[tt] = 0.0f;
            for (int i = 0; i < 8; i++) {
                float xv[20];
                const float4* p = (const float4*)(in + i * WROW + t0);
                #pragma unroll
                for (int q = 0; q < 5; q++) {
                    float4 v = p[q];
                    xv[4*q+0] = v.x; xv[4*q+1] = v.y;
                    xv[4*q+2] = v.z; xv[4*q+3] = v.w;
                }
                #pragma unroll
                for (int k = 0; k < 4; k++) {
                    float wk = w2s[(i * 4 + k) * 8 + o];
                    #pragma unroll
                    for (int tt = 0; tt < 16; tt++)
                        acc[tt] = fmaf(xv[tt + k], wk, acc[tt]);
                }
            }
            float bo = b2s[o];
            #pragma unroll
            for (int tt = 0; tt < 16; tt++)
                if (tt < count) outp[o * WROW + t0 + tt] = fmaxf(acc[tt] + bo, 0.0f);
        }
        __syncwarp();
        // ---- conv3 (no relu): H2 -> H3, Lout=55; window = 2x LDS.128 ----
        {
            const float* in = S + H2_OFF;
            float* outp = S + H3_OFF;
            int o = lane >> 4, g = lane & 15, t0 = g * 4;
            int count = 55 - t0; count = count > 4 ? 4 : (count < 0 ? 0 : count);
            float acc[4] = {0.f, 0.f, 0.f, 0.f};
            for (int i = 0; i < 8; i++) {
                float xv[8];
                const float4* p = (const float4*)(in + i * WROW + t0);
                #pragma unroll
                for (int q = 0; q < 2; q++) {
                    float4 v = p[q];
                    xv[4*q+0] = v.x; xv[4*q+1] = v.y;
                    xv[4*q+2] = v.z; xv[4*q+3] = v.w;
                }
                #pragma unroll
                for (int k = 0; k < 4; k++) {
                    float wk = w3s[(i * 4 + k) * 2 + o];
                    #pragma unroll
                    for (int tt = 0; tt < 4; tt++)
                        acc[tt] = fmaf(xv[tt + k], wk, acc[tt]);
                }
            }
            float bo = b3s[o];
            #pragma unroll
            for (int tt = 0; tt < 4; tt++)
                if (tt < count) outp[o * 56 + t0 + tt] = acc[tt] + bo;
        }
        __syncwarp();
    }

    // ---- sig1 endpoint captured before aliasing ----
    float sig1v = 0.0f;
    if (bvalid && lane < CC) {
        if (lane < 8)       sig1v = S[XS_OFF + lane * WROW + 63];
        else if (lane == 8) sig1v = 1.0f;
        else                sig1v = S[H3_OFF + (lane - 9) * 56 + 54];
    }

    // ---- i-fixed slot map: lane owns (i_lane, j = 4*quad + m), m=0..3.
    //      lanes 0-10: i=lane,  j 0-3 ; 11-21: i=lane-11, j 4-7 ;
    //      22-31: i=lane-22, j 8-11 (j=11 reads pad 0 -> exact no-op).
    //      Missing slots (10,8),(10,9),(10,10) -> shuffle-identity epilogue. ----
    const int quad   = (lane < 11) ? 0 : (lane < 22) ? 1 : 2;
    const int i_lane = lane - 11 * quad;

    float s1i = 0.0f;
    float s2[4] = {0.f, 0.f, 0.f, 0.f};
    unsigned long long s3p[4][6];
    #pragma unroll
    for (int m = 0; m < 4; m++)
        #pragma unroll
        for (int q = 0; q < 6; q++) s3p[m][q] = 0ULL;

    if (bvalid) {
        // ---- dx[t][c] (c=0..10, col 11 = 0 pad) into DXS ----
        for (int idx = lane; idx < 55 * 12; idx += 32) {
            int t = idx / 12, c = idx - t * 12;
            float v;
            if (c < 8) {
                v = (t == 0) ? S[XS_OFF + c * WROW + 9]
                             : S[XS_OFF + c * WROW + 9 + t] - S[XS_OFF + c * WROW + 8 + t];
            } else if (c == 8) {
                v = (t == 0) ? 0.0f : (1.0f / 54.0f);
            } else if (c < 11) {
                int o = c - 9;
                v = (t == 0) ? S[H3_OFF + o * 56]
                             : S[H3_OFF + o * 56 + t] - S[H3_OFF + o * 56 + t - 1];
            } else {
                v = 0.0f;
            }
            S[DXS_OFF + idx] = v;
        }
        __syncwarp();

        // ---- signature main loop (factored Chen, packed f32x2), unroll 5.
        //      di: 1 scalar LDS (11 distinct words, 1 wf).
        //      dj quad: 1 aligned LDS.128 (3 distinct addrs).
        //      c1/c2/s1 shared across the lane's 4 slots. ----
        const float* dxbase = S + DXS_OFF;
        #pragma unroll 5
        for (int t = 0; t < LO; t++) {
            const float* row = dxbase + t * 12;
            ulonglong2 a0 = *(const ulonglong2*)(row);
            ulonglong2 a1 = *(const ulonglong2*)(row + 4);
            ulonglong2 a2 = *(const ulonglong2*)(row + 8);
            unsigned long long dp[6] = {a0.x, a0.y, a1.x, a1.y, a2.x, a2.y};
            float4 djv = *(const float4*)(row + 4 * quad);
            float di = row[i_lane];

            float c1 = fmaf(1.0f / 6.0f, di, 0.5f * s1i);
            float c2 = fmaf(0.5f, di, s1i);
            s1i += di;

            float dj[4] = {djv.x, djv.y, djv.z, djv.w};
            #pragma unroll
            for (int m = 0; m < 4; m++) {
                float Mv = fmaf(dj[m], c1, s2[m]);
                s2[m]    = fmaf(dj[m], c2, s2[m]);
                unsigned long long mvp = pack2(Mv, Mv);
                #pragma unroll
                for (int q = 0; q < 6; q++)
                    fma2(s3p[m][q], dp[q], mvp);
            }
        }
        __syncwarp();

        // ---- scatter signature to shared (conflict-free) ----
        float* sig = S + SIG_OFF;
        if (lane < CC) sig[lane] = sig1v;
        for (int z = SIGCH + lane; z < SIGPAD; z += 32) sig[z] = 0.0f;
        #pragma unroll
        for (int m = 0; m < 4; m++) {
            int j = 4 * quad + m;
            if (j < CC) {
                int ij = i_lane * 11 + j;
                sig[CC + ij] = s2[m];
                #pragma unroll
                for (int q = 0; q < 6; q++) {
                    float lo, hi;
                    unpack2(s3p[m][q], lo, hi);
                    int k = 2 * q;
                    sig[CC + CC2 + ij * 11 + k] = lo;
                    if (k + 1 < 11) sig[CC + CC2 + ij * 11 + k + 1] = hi;
                }
            }
        }
        __syncwarp();

        // ---- shuffle-identity reconstruction of (10,8),(10,9),(10,10) ----
        {
            float* sg2 = sig + CC;
            float* sg3 = sig + CC + CC2;
            float s1_10 = sig[10];
            // step1: s2[10,k] for k = 8,9,10 via s2[ab]+s2[ba]=s1a*s1b
            if (lane >= 8 && lane < CC) {
                int k = lane;
                float v = (k == 10) ? 0.5f * s1_10 * s1_10
                                    : s1_10 * sig[k] - sg2[k * 11 + 10];
                sg2[110 + k] = v;
            }
            __syncwarp();
            // step2: s3[10,j,k] = s1_10*s2[j,k] - s3[j,10,k] - s3[j,k,10], j=8,9
            if (lane < CC) {
                int k = lane;
                #pragma unroll
                for (int j = 8; j <= 9; j++) {
                    float v = s1_10 * sg2[j * 11 + k]
                            - sg3[(j * 11 + 10) * 11 + k]
                            - sg3[(j * 11 + k) * 11 + 10];
                    sg3[(110 + j) * 11 + k] = v;
                }
            }
            __syncwarp();
            // step3: s3[10,10,k] = (s1_10*s2[10,k] - s3[10,k,10]) / 2 ; k=10: s1*s2[10,10]/3
            if (lane < CC) {
                int k = lane;
                float v;
                if (k == 10) v = s1_10 * sg2[120] * (1.0f / 3.0f);
                else         v = 0.5f * (s1_10 * sg2[110 + k]
                                         - sg3[(110 + k) * 11 + 10]);
                sg3[120 * 11 + k] = v;
            }
        }
    }
    __syncthreads();

    // ---- block-cooperative head: warps split stocks {3,3,2,2}; each warp
    //      applies its stocks' weights to ALL 4 batch sigs (Wl read once).
    //      128-bit loads: 4 channels/lane/iter. ----
    const int s_base = (warp < 2) ? warp * 3 : 6 + (warp - 2) * 2;
    const int n_s    = (warp < 2) ? 3 : 2;

    unsigned long long acc[4][3];
    #pragma unroll
    for (int bb = 0; bb < 4; bb++)
        #pragma unroll
        for (int sl = 0; sl < 3; sl++) acc[bb][sl] = 0ULL;

    const float* wl = g_WlPad;
    for (int it = 0; it < SIGPAD / 128; it++) {
        int c = 4 * lane + 128 * it;
        ulonglong2 vp[4];
        #pragma unroll
        for (int bb = 0; bb < 4; bb++)
            vp[bb] = *(const ulonglong2*)(wmem + bb * WARP_FLTS + SIG_OFF + c);
        #pragma unroll
        for (int sl = 0; sl < 3; sl++) {
            if (sl < n_s) {
                ulonglong2 wp =
                    *(const ulonglong2*)(wl + (s_base + sl) * SIGPAD + c);
                #pragma unroll
                for (int bb = 0; bb < 4; bb++) {
                    fma2(acc[bb][sl], vp[bb].x, wp.x);
                    fma2(acc[bb][sl], vp[bb].y, wp.y);
                }
            }
        }
    }

    #pragma unroll
    for (int bb = 0; bb < 4; bb++) {
        int bg = blockIdx.x * WARPS + bb;
        #pragma unroll
        for (int sl = 0; sl < 3; sl++) {
            if (sl < n_s) {
                float lo, hi;
                unpack2(acc[bb][sl], lo, hi);
                float v = lo + hi;
                #pragma unroll
                for (int off = 16; off > 0; off >>= 1)
                    v += __shfl_xor_sync(0xffffffffu, v, off);
                if (lane == 0 && bg < B)
                    out[bg * NSTOCK + s_base + sl] = v + __ldg(&bl[s_base + sl]);
            }
        }
    }
}

extern "C" void kernel_launch(void* const* d_in, const int* in_sizes, int n_in,
                              void* d_out, int out_size)
{
    const float* x  = (const float*)d_in[0];
    const float* W1 = (const float*)d_in[1];
    const float* b1 = (const float*)d_in[2];
    const float* W2 = (const float*)d_in[3];
    const float* b2 = (const float*)d_in[4];
    const float* W3 = (const float*)d_in[5];
    const float* b3 = (const float*)d_in[6];
    const float* Wl = (const float*)d_in[7];
    const float* bl = (const float*)d_in[8];
    float* out = (float*)d_out;

    int B = in_sizes[0] / (LFULL * CIN);   // 8192

    wl_pad_kernel<<<(NSTOCK * SIGPAD + 255) / 256, 256>>>(Wl);

    int blocks = (B + WARPS - 1) / WARPS;
    deepsig_kernel<<<blocks, NTHREADS>>>(x, W1, b1, W2, b2, W3, b3, bl, out, B);
}

// round 16
// speedup vs baseline: 1.0879x; 1.0112x over previous
#include <cuda_runtime.h>

// B=8192, L=64, Cin=8, KS=4, trunc=9, Lo=55, Caug=11, DEPTH=3
// sig = 11 + 121 + 1331 = 1463 channels; head 1463 -> 10
#define WARPS    4
#define NTHREADS (32 * WARPS)
#define LFULL    64
#define CIN      8
#define LO       55
#define CC       11
#define CC2      121
#define SIGCH    1463
#define SIGPAD   1536            // 12 * 128
#define NSTOCK   10

// per-warp shared region (floats); rows pitched 68 (16B-aligned float4 rows)
#define WROW     68
#define XS_OFF   0               // x transposed [c][t], 8*68
#define H1_OFF   544             // conv1 out, 8*68
#define H2_OFF   1088            // conv2 out, 8*68
#define H3_OFF   1632            // conv3 out, 2*56
#define DXS_OFF  544             // aliases H1/H2 (dead after conv3), 55*12
#define SIG_OFF  0               // aliases XS/H1/DXS after main loop, 1536
#define WARP_FLTS 1744

__device__ __align__(16) float g_WlPad[NSTOCK * SIGPAD];

__global__ void wl_pad_kernel(const float* __restrict__ Wl)
{
    int idx = blockIdx.x * blockDim.x + threadIdx.x;
    if (idx < NSTOCK * SIGPAD) {
        int s = idx / SIGPAD, c = idx - s * SIGPAD;
        g_WlPad[idx] = (c < SIGCH) ? Wl[s * SIGCH + c] : 0.0f;
    }
}

__device__ __forceinline__ unsigned long long pack2(float lo, float hi)
{
    unsigned long long r;
    asm("mov.b64 %0, {%1, %2};" : "=l"(r) : "f"(lo), "f"(hi));
    return r;
}
__device__ __forceinline__ void unpack2(unsigned long long v, float& lo, float& hi)
{
    asm("mov.b64 {%0, %1}, %2;" : "=f"(lo), "=f"(hi) : "l"(v));
}
__device__ __forceinline__ void fma2(unsigned long long& d,
                                     unsigned long long a, unsigned long long b)
{
    asm("fma.rn.f32x2 %0, %1, %2, %0;" : "+l"(d) : "l"(a), "l"(b));
}

__global__ void __launch_bounds__(NTHREADS, 5)
deepsig_kernel(const float* __restrict__ x,
               const float* __restrict__ W1, const float* __restrict__ b1,
               const float* __restrict__ W2, const float* __restrict__ b2,
               const float* __restrict__ W3, const float* __restrict__ b3,
               const float* __restrict__ bl,
               float* __restrict__ out, int B)
{
    __shared__ __align__(16) float wmem[WARPS * WARP_FLTS];
    __shared__ float w1s[256], w2s[256], w3s[64], b1s[8], b2s[8], b3s[2];

    const int tid  = threadIdx.x;
    const int warp = tid >> 5;
    const int lane = tid & 31;

    // Stage conv weights transposed: ws[(i*4+k)*OC + o] = W[o][i][k]
    for (int i = tid; i < 256; i += NTHREADS) {
        int o = i >> 5, r = i & 31;
        w1s[r * 8 + o] = W1[i];
        w2s[r * 8 + o] = W2[i];
    }
    for (int i = tid; i < 64; i += NTHREADS) {
        int o = i >> 5, r = i & 31;
        w3s[r * 2 + o] = W3[i];
    }
    if (tid < 8) { b1s[tid] = b1[tid]; b2s[tid] = b2[tid]; }
    if (tid < 2) { b3s[tid] = b3[tid]; }
    __syncthreads();

    const int b = blockIdx.x * WARPS + warp;
    const bool bvalid = (b < B);

    float* S = wmem + warp * WARP_FLTS;

    if (bvalid) {
        // ---- Load x (float4, coalesced), transpose into [c][t] pitch 68 ----
        const float4* xb4 = (const float4*)(x + (size_t)b * (LFULL * CIN));
        #pragma unroll
        for (int it = 0; it < 4; it++) {
            int idx = (lane + it * 32);
            int t = idx >> 1, c = (idx & 1) * 4;
            float4 v = xb4[idx];
            S[XS_OFF + (c + 0) * WROW + t] = v.x;
            S[XS_OFF + (c + 1) * WROW + t] = v.y;
            S[XS_OFF + (c + 2) * WROW + t] = v.z;
            S[XS_OFF + (c + 3) * WROW + t] = v.w;
        }
        __syncwarp();

        // ---- conv1 (relu): XS -> H1, Lout=61; window = 5x LDS.128 ----
        {
            const float* in = S + XS_OFF;
            float* outp = S + H1_OFF;
            int o = lane >> 2, g = lane & 3, t0 = g * 16;
            int count = 61 - t0; if (count > 16) count = 16;
            float acc[16];
            #pragma unroll
            for (int tt = 0; tt < 16; tt++) acc[tt] = 0.0f;
            for (int i = 0; i < 8; i++) {
                float xv[20];
                const float4* p = (const float4*)(in + i * WROW + t0);
                #pragma unroll
                for (int q = 0; q < 5; q++) {
                    float4 v = p[q];
                    xv[4*q+0] = v.x; xv[4*q+1] = v.y;
                    xv[4*q+2] = v.z; xv[4*q+3] = v.w;
                }
                #pragma unroll
                for (int k = 0; k < 4; k++) {
                    float wk = w1s[(i * 4 + k) * 8 + o];
                    #pragma unroll
                    for (int tt = 0; tt < 16; tt++)
                        acc[tt] = fmaf(xv[tt + k], wk, acc[tt]);
                }
            }
            float bo = b1s[o];
            #pragma unroll
            for (int tt = 0; tt < 16; tt++)
                if (tt < count) outp[o * WROW + t0 + tt] = fmaxf(acc[tt] + bo, 0.0f);
        }
        __syncwarp();
        // ---- conv2 (relu): H1 -> H2, Lout=58 ----
        {
            const float* in = S + H1_OFF;
            float* outp = S + H2_OFF;
            int o = lane >> 2, g = lane & 3, t0 = g * 16;
            int count = 58 - t0; if (count > 16) count = 16;
            float acc[16];
            #pragma unroll
            for (int tt = 0; tt < 16; tt++) acc[tt] = 0.0f;
            for (int i = 0; i < 8; i++) {
                float xv[20];
                const float4* p = (const float4*)(in + i * WROW + t0);
                #pragma unroll
                for (int q = 0; q < 5; q++) {
                    float4 v = p[q];
                    xv[4*q+0] = v.x; xv[4*q+1] = v.y;
                    xv[4*q+2] = v.z; xv[4*q+3] = v.w;
                }
                #pragma unroll
                for (int k = 0; k < 4; k++) {
                    float wk = w2s[(i * 4 + k) * 8 + o];
                    #pragma unroll
                    for (int tt = 0; tt < 16; tt++)
                        acc[tt] = fmaf(xv[tt + k], wk, acc[tt]);
                }
            }
            float bo = b2s[o];
            #pragma unroll
            for (int tt = 0; tt < 16; tt++)
                if (tt < count) outp[o * WROW + t0 + tt] = fmaxf(acc[tt] + bo, 0.0f);
        }
        __syncwarp();
        // ---- conv3 (no relu): H2 -> H3, Lout=55; window = 2x LDS.128 ----
        {
            const float* in = S + H2_OFF;
            float* outp = S + H3_OFF;
            int o = lane >> 4, g = lane & 15, t0 = g * 4;
            int count = 55 - t0; count = count > 4 ? 4 : (count < 0 ? 0 : count);
            float acc[4] = {0.f, 0.f, 0.f, 0.f};
            for (int i = 0; i < 8; i++) {
                float xv[8];
                const float4* p = (const float4*)(in + i * WROW + t0);
                #pragma unroll
                for (int q = 0; q < 2; q++) {
                    float4 v = p[q];
                    xv[4*q+0] = v.x; xv[4*q+1] = v.y;
                    xv[4*q+2] = v.z; xv[4*q+3] = v.w;
                }
                #pragma unroll
                for (int k = 0; k < 4; k++) {
                    float wk = w3s[(i * 4 + k) * 2 + o];
                    #pragma unroll
                    for (int tt = 0; tt < 4; tt++)
                        acc[tt] = fmaf(xv[tt + k], wk, acc[tt]);
                }
            }
            float bo = b3s[o];
            #pragma unroll
            for (int tt = 0; tt < 4; tt++)
                if (tt < count) outp[o * 56 + t0 + tt] = acc[tt] + bo;
        }
        __syncwarp();
    }

    // ---- sig1 endpoint captured before aliasing ----
    float sig1v = 0.0f;
    if (bvalid && lane < CC) {
        if (lane < 8)       sig1v = S[XS_OFF + lane * WROW + 63];
        else if (lane == 8) sig1v = 1.0f;
        else                sig1v = S[H3_OFF + (lane - 9) * 56 + 54];
    }

    // ---- i-fixed slot map: lane owns (i_lane, j = 4*quad + m), m=0..3.
    //      lanes 0-10: i=lane,  j 0-3 ; 11-21: i=lane-11, j 4-7 ;
    //      22-31: i=lane-22, j 8-11 (j=11 reads pad 0 -> exact no-op).
    //      Missing slots (10,8),(10,9),(10,10) -> shuffle-identity epilogue. ----
    const int quad   = (lane < 11) ? 0 : (lane < 22) ? 1 : 2;
    const int i_lane = lane - 11 * quad;

    float s1i = 0.0f;
    float s2[4] = {0.f, 0.f, 0.f, 0.f};
    unsigned long long s3p[4][6];
    #pragma unroll
    for (int m = 0; m < 4; m++)
        #pragma unroll
        for (int q = 0; q < 6; q++) s3p[m][q] = 0ULL;

    if (bvalid) {
        // ---- dx[t][c] (c=0..10, col 11 = 0 pad) into DXS ----
        for (int idx = lane; idx < 55 * 12; idx += 32) {
            int t = idx / 12, c = idx - t * 12;
            float v;
            if (c < 8) {
                v = (t == 0) ? S[XS_OFF + c * WROW + 9]
                             : S[XS_OFF + c * WROW + 9 + t] - S[XS_OFF + c * WROW + 8 + t];
            } else if (c == 8) {
                v = (t == 0) ? 0.0f : (1.0f / 54.0f);
            } else if (c < 11) {
                int o = c - 9;
                v = (t == 0) ? S[H3_OFF + o * 56]
                             : S[H3_OFF + o * 56 + t] - S[H3_OFF + o * 56 + t - 1];
            } else {
                v = 0.0f;
            }
            S[DXS_OFF + idx] = v;
        }
        __syncwarp();

        // ---- signature main loop (factored Chen, packed f32x2), unroll 5.
        //      di: 1 scalar LDS (11 distinct words, 1 wf).
        //      dj quad: 1 aligned LDS.128 (3 distinct addrs).
        //      c1/c2/s1 shared across the lane's 4 slots. ----
        const float* dxbase = S + DXS_OFF;
        #pragma unroll 5
        for (int t = 0; t < LO; t++) {
            const float* row = dxbase + t * 12;
            ulonglong2 a0 = *(const ulonglong2*)(row);
            ulonglong2 a1 = *(const ulonglong2*)(row + 4);
            ulonglong2 a2 = *(const ulonglong2*)(row + 8);
            unsigned long long dp[6] = {a0.x, a0.y, a1.x, a1.y, a2.x, a2.y};
            float4 djv = *(const float4*)(row + 4 * quad);
            float di = row[i_lane];

            float c1 = fmaf(1.0f / 6.0f, di, 0.5f * s1i);
            float c2 = fmaf(0.5f, di, s1i);
            s1i += di;

            float dj[4] = {djv.x, djv.y, djv.z, djv.w};
            #pragma unroll
            for (int m = 0; m < 4; m++) {
                float Mv = fmaf(dj[m], c1, s2[m]);
                s2[m]    = fmaf(dj[m], c2, s2[m]);
                unsigned long long mvp = pack2(Mv, Mv);
                #pragma unroll
                for (int q = 0; q < 6; q++)
                    fma2(s3p[m][q], dp[q], mvp);
            }
        }
        __syncwarp();

        // ---- scatter signature to shared (conflict-free) ----
        float* sig = S + SIG_OFF;
        if (lane < CC) sig[lane] = sig1v;
        for (int z = SIGCH + lane; z < SIGPAD; z += 32) sig[z] = 0.0f;
        #pragma unroll
        for (int m = 0; m < 4; m++) {
            int j = 4 * quad + m;
            if (j < CC) {
                int ij = i_lane * 11 + j;
                sig[CC + ij] = s2[m];
                #pragma unroll
                for (int q = 0; q < 6; q++) {
                    float lo, hi;
                    unpack2(s3p[m][q], lo, hi);
                    int k = 2 * q;
                    sig[CC + CC2 + ij * 11 + k] = lo;
                    if (k + 1 < 11) sig[CC + CC2 + ij * 11 + k + 1] = hi;
                }
            }
        }
        __syncwarp();

        // ---- shuffle-identity reconstruction of (10,8),(10,9),(10,10) ----
        {
            float* sg2 = sig + CC;
            float* sg3 = sig + CC + CC2;
            float s1_10 = sig[10];
            // step1: s2[10,k] for k = 8,9,10 via s2[ab]+s2[ba]=s1a*s1b
            if (lane >= 8 && lane < CC) {
                int k = lane;
                float v = (k == 10) ? 0.5f * s1_10 * s1_10
                                    : s1_10 * sig[k] - sg2[k * 11 + 10];
                sg2[110 + k] = v;
            }
            __syncwarp();
            // step2: s3[10,j,k] = s1_10*s2[j,k] - s3[j,10,k] - s3[j,k,10], j=8,9
            if (lane < CC) {
                int k = lane;
                #pragma unroll
                for (int j = 8; j <= 9; j++) {
                    float v = s1_10 * sg2[j * 11 + k]
                            - sg3[(j * 11 + 10) * 11 + k]
                            - sg3[(j * 11 + k) * 11 + 10];
                    sg3[(110 + j) * 11 + k] = v;
                }
            }
            __syncwarp();
            // step3: s3[10,10,k] = (s1_10*s2[10,k] - s3[10,k,10]) / 2 ; k=10: s1*s2[10,10]/3
            if (lane < CC) {
                int k = lane;
                float v;
                if (k == 10) v = s1_10 * sg2[120] * (1.0f / 3.0f);
                else         v = 0.5f * (s1_10 * sg2[110 + k]
                                         - sg3[(110 + k) * 11 + 10]);
                sg3[120 * 11 + k] = v;
            }
        }
    }
    __syncthreads();

    // ---- block-cooperative head: warps split stocks {3,3,2,2}; each warp
    //      applies its stocks' weights to ALL 4 batch sigs (Wl read once).
    //      128-bit loads: 4 channels/lane/iter. ----
    const int s_base = (warp < 2) ? warp * 3 : 6 + (warp - 2) * 2;
    const int n_s    = (warp < 2) ? 3 : 2;

    unsigned long long acc[4][3];
    #pragma unroll
    for (int bb = 0; bb < 4; bb++)
        #pragma unroll
        for (int sl = 0; sl < 3; sl++) acc[bb][sl] = 0ULL;

    const float* wl = g_WlPad;
    for (int it = 0; it < SIGPAD / 128; it++) {
        int c = 4 * lane + 128 * it;
        ulonglong2 vp[4];
        #pragma unroll
        for (int bb = 0; bb < 4; bb++)
            vp[bb] = *(const ulonglong2*)(wmem + bb * WARP_FLTS + SIG_OFF + c);
        #pragma unroll
        for (int sl = 0; sl < 3; sl++) {
            if (sl < n_s) {
                ulonglong2 wp =
                    *(const ulonglong2*)(wl + (s_base + sl) * SIGPAD + c);
                #pragma unroll
                for (int bb = 0; bb < 4; bb++) {
                    fma2(acc[bb][sl], vp[bb].x, wp.x);
                    fma2(acc[bb][sl], vp[bb].y, wp.y);
                }
            }
        }
    }

    #pragma unroll
    for (int bb = 0; bb < 4; bb++) {
        int bg = blockIdx.x * WARPS + bb;
        #pragma unroll
        for (int sl = 0; sl < 3; sl++) {
            if (sl < n_s) {
                float lo, hi;
                unpack2(acc[bb][sl], lo, hi);
                float v = lo + hi;
                #pragma unroll
                for (int off = 16; off > 0; off >>= 1)
                    v += __shfl_xor_sync(0xffffffffu, v, off);
                if (lane == 0 && bg < B)
                    out[bg * NSTOCK + s_base + sl] = v + __ldg(&bl[s_base + sl]);
            }
        }
    }
}

extern "C" void kernel_launch(void* const* d_in, const int* in_sizes, int n_in,
                              void* d_out, int out_size)
{
    const float* x  = (const float*)d_in[0];
    const float* W1 = (const float*)d_in[1];
    const float* b1 = (const float*)d_in[2];
    const float* W2 = (const float*)d_in[3];
    const float* b2 = (const float*)d_in[4];
    const float* W3 = (const float*)d_in[5];
    const float* b3 = (const float*)d_in[6];
    const float* Wl = (const float*)d_in[7];
    const float* bl = (const float*)d_in[8];
    float* out = (float*)d_out;

    int B = in_sizes[0] / (LFULL * CIN);   // 8192

    wl_pad_kernel<<<(NSTOCK * SIGPAD + 255) / 256, 256>>>(Wl);

    int blocks = (B + WARPS - 1) / WARPS;
    deepsig_kernel<<<blocks, NTHREADS>>>(x, W1, b1, W2, b2, W3, b3, bl, out, B);
}